// round 7
// baseline (speedup 1.0000x reference)
#include <cuda_runtime.h>
#include <cuda_fp16.h>
#include <cstdint>
#include <cstddef>

// XOR-conv implicit GEMM, mma.sync fp16 (f32 acc).
// R7: weights pre-swizzled into MMA A-fragment order -> LDG.128 straight to
// registers (no smem, no cp.async for weights); barriers only per ci-chunk.
#define BB 32
#define CIN 128
#define HH 64
#define WWD 64
#define COUT 256
#define HOUT 62
#define WOUT 62

// A-fragments: [khw 9][cob 2][chunk 4][wm 4][lane 32][ci16 2][mi 2][w 4] u32
__device__ __align__(16) uint32_t g_wfrag[9 * 2 * 4 * 4 * 32 * 16];
__device__ __align__(16) uint32_t g_xh[(size_t)BB * HH * WWD * 64];  // fp16x2 [b][h][w][ci/2]

__device__ __forceinline__ uint32_t smem_u32(const void* p) {
    uint32_t a;
    asm("{ .reg .u64 t; cvta.to.shared.u64 t, %1; cvt.u32.u64 %0, t; }" : "=r"(a) : "l"(p));
    return a;
}
__device__ __forceinline__ void cpa16(uint32_t dst, const void* src, uint32_t sz) {
    asm volatile("cp.async.cg.shared.global [%0], [%1], 16, %2;"
                 :: "r"(dst), "l"(src), "r"(sz) : "memory");
}
__device__ __forceinline__ void ldsm_x4(uint32_t* r, uint32_t a) {
    asm volatile("ldmatrix.sync.aligned.m8n8.x4.shared.b16 {%0,%1,%2,%3}, [%4];"
                 : "=r"(r[0]), "=r"(r[1]), "=r"(r[2]), "=r"(r[3]) : "r"(a));
}
#define MMA16816(c, A, b0, b1)                                                \
    asm volatile("mma.sync.aligned.m16n8k16.row.col.f32.f16.f16.f32 "         \
                 "{%0,%1,%2,%3}, {%4,%5,%6,%7}, {%8,%9}, {%0,%1,%2,%3};"      \
                 : "+f"((c)[0]), "+f"((c)[1]), "+f"((c)[2]), "+f"((c)[3])     \
                 : "r"((A)[0]), "r"((A)[1]), "r"((A)[2]), "r"((A)[3]),        \
                   "r"(b0), "r"(b1))

// ---------------- prep ----------------
__global__ void prep_w_kernel(const float* __restrict__ w) {
    int t = blockIdx.x * 256 + threadIdx.x;
    if (t >= 9 * 256 * 64) return;
    int khw = t >> 14, r = t & 16383;
    int co = r >> 6, ci = (r & 63) * 2;
    int kh = khw / 3, kw = khw % 3;
    const float* wp = w + (((size_t)co * CIN + ci) * 3 + kh) * 3 + kw;
    float v0 = 1.0f - 2.0f * wp[0];
    float v1 = 1.0f - 2.0f * wp[9];      // ci+1
    uint32_t pk = ((uint32_t)__half_as_ushort(__float2half_rn(v1)) << 16) |
                  __half_as_ushort(__float2half_rn(v0));
    int cob = co >> 7, chunk = ci >> 5, wm = (co >> 5) & 3, mi = (co >> 4) & 1;
    int lane = ((co & 7) << 2) | ((ci >> 1) & 3);
    int wrd  = (((ci >> 3) & 1) << 1) | ((co >> 3) & 1);
    int ci16 = (ci >> 4) & 1;
    int idx = ((((((khw * 2 + cob) * 4 + chunk) * 4 + wm) * 32 + lane) * 2 + ci16) * 2 + mi) * 4 + wrd;
    g_wfrag[idx] = pk;
}

__global__ void prep_x_kernel(const float* __restrict__ x) {
    __shared__ float t[CIN][67];
    const int h = blockIdx.x, b = blockIdx.y, tid = threadIdx.x;
#pragma unroll
    for (int i = 0; i < 32; i++) {
        int idx = tid + i * 256;
        int ci = idx >> 6, w = idx & 63;
        t[ci][w] = x[(((size_t)b * CIN + ci) * HH + h) * WWD + w];
    }
    __syncthreads();
#pragma unroll
    for (int i = 0; i < 16; i++) {
        int idx = tid + i * 256;
        int w = idx >> 6, j = idx & 63;
        uint32_t hw2 = ((uint32_t)__half_as_ushort(__float2half_rn(t[2 * j + 1][w])) << 16) |
                       __half_as_ushort(__float2half_rn(t[2 * j][w]));
        g_xh[(((size_t)b * HH + h) * WWD + w) * 64 + j] = hw2;
    }
}

// ---------------- main ----------------
#define POS_STRIDE 80
#define XBUFSZ (6 * 66 * POS_STRIDE)      // 31680
#define SMEM_TOTAL (2 * XBUFSZ)           // 63360

__global__ __launch_bounds__(512, 1)
void xorconv_mma_kernel(float* __restrict__ out) {
    extern __shared__ char smraw[];
    const uint32_t SX = smem_u32(smraw);

    const int tid = threadIdx.x;
    const int wid = tid >> 5, lid = tid & 31;
    const int wm = wid & 3;           // 32-co sub-tile
    const int wn = wid >> 2;          // ho row 0..3
    const int ho0 = blockIdx.x * 4;
    const int cob = blockIdx.y;       // 128-co block
    const int b = blockIdx.z;

    const int li = lid & 7, g = lid >> 3;
    uint32_t qb[4];
#pragma unroll
    for (int j = 0; j < 4; j++)
        qb[j] = (uint32_t)(j * 16 + ((g >> 1) & 1) * 8 + li) * POS_STRIDE + (g & 1) * 16;

    float acc[2][8][4];
#pragma unroll
    for (int mi = 0; mi < 2; mi++)
#pragma unroll
        for (int ni = 0; ni < 8; ni++)
#pragma unroll
            for (int e = 0; e < 4; e++) acc[mi][ni][e] = 0.0f;

    auto stage_x = [&](int q) {       // 32 ci into xbuf[q&1]
        const uint32_t xb = SX + (uint32_t)(q & 1) * XBUFSZ;
#pragma unroll
        for (int i = 0; i < 4; i++) {
            int idx = tid + i * 512;
            if (idx < 1584) {
                int pos = idx >> 2, c4 = idx & 3;
                int hl = pos / 66, w = pos - hl * 66;
                int h = ho0 + hl;
                uint32_t sz = (h < HH && w < WWD) ? 16u : 0u;
                size_t eo = ((((size_t)b * HH + (h & 63)) * WWD + (w & 63)) * 64) + q * 16 + c4 * 4;
                cpa16(xb + (uint32_t)pos * POS_STRIDE + c4 * 16,
                      (const char*)g_xh + eo * 4, sz);
            }
        }
        asm volatile("cp.async.commit_group;" ::: "memory");
    };

    // 4 x uint4 LDG of this warp-lane's A fragments for (chunk q, khw)
    auto preload = [&](int q, int khw, uint32_t* wf) {
        const uint4* p = (const uint4*)g_wfrag +
            (size_t)((((khw * 2 + cob) * 4 + q) * 4 + wm) * 32 + lid) * 4;
        uint4 v0 = p[0], v1 = p[1], v2 = p[2], v3 = p[3];
        wf[0] = v0.x;  wf[1] = v0.y;  wf[2] = v0.z;  wf[3] = v0.w;
        wf[4] = v1.x;  wf[5] = v1.y;  wf[6] = v1.z;  wf[7] = v1.w;
        wf[8] = v2.x;  wf[9] = v2.y;  wf[10] = v2.z; wf[11] = v2.w;
        wf[12] = v3.x; wf[13] = v3.y; wf[14] = v3.z; wf[15] = v3.w;
    };

    stage_x(0);

    for (int q = 0; q < 4; q++) {
        asm volatile("cp.async.wait_group 0;" ::: "memory");
        __syncthreads();
        if (q < 3) stage_x(q + 1);    // overlaps this chunk's 9 compute iters

        const uint32_t xb = SX + (uint32_t)(q & 1) * XBUFSZ;
        uint32_t wf[2][16];
        preload(q, 0, wf[0]);

#pragma unroll
        for (int khw = 0; khw < 9; khw++) {
            if (khw < 8) preload(q, khw + 1, wf[(khw + 1) & 1]);
            const int kh = khw / 3, kw = khw % 3;
            const uint32_t hwoff = (uint32_t)((wn + kh) * 66 + kw) * POS_STRIDE;
            uint32_t* wfc = wf[khw & 1];

#pragma unroll
            for (int ci16 = 0; ci16 < 2; ci16++) {
                const uint32_t xsel = xb + ci16 * 32 + hwoff;
                uint32_t* a0 = wfc + ci16 * 8;       // mi=0 frags
                uint32_t* a1 = wfc + ci16 * 8 + 4;   // mi=1 frags
#pragma unroll
                for (int j = 0; j < 4; j++) {
                    uint32_t bx[4];
                    ldsm_x4(bx, xsel + qb[j]);
                    MMA16816(acc[0][2 * j], a0, bx[0], bx[1]);
                    MMA16816(acc[0][2 * j + 1], a0, bx[2], bx[3]);
                    MMA16816(acc[1][2 * j], a1, bx[0], bx[1]);
                    MMA16816(acc[1][2 * j + 1], a1, bx[2], bx[3]);
                }
            }
        }
    }

    // ---- epilogue (unchanged) ----
    const int row = lid >> 2, qp = lid & 3;
    const int ho = ho0 + wn;
    if (ho < HOUT) {
#pragma unroll
        for (int mi = 0; mi < 2; mi++) {
            const int cor = cob * 128 + wm * 32 + mi * 16 + row;
            float* b0p = out + (((size_t)b * COUT + cor) * HOUT + ho) * WOUT;
            float* b1p = out + (((size_t)b * COUT + cor + 8) * HOUT + ho) * WOUT;
#pragma unroll
            for (int ni = 0; ni < 8; ni++) {
                const int wo = ni * 8 + qp * 2;
                if (wo < WOUT) {
                    *(float2*)(b0p + wo) = make_float2(acc[mi][ni][0], acc[mi][ni][1]);
                    *(float2*)(b1p + wo) = make_float2(acc[mi][ni][2], acc[mi][ni][3]);
                }
            }
        }
    }
}

// ---------------- launch ----------------
extern "C" void kernel_launch(void* const* d_in, const int* in_sizes, int n_in,
                              void* d_out, int out_size) {
    const float* x = (const float*)d_in[0];
    const float* w = (const float*)d_in[1];
    float* out = (float*)d_out;

    prep_w_kernel<<<(9 * 256 * 64 + 255) / 256, 256>>>(w);
    prep_x_kernel<<<dim3(HH, BB), 256>>>(x);

    cudaFuncSetAttribute(xorconv_mma_kernel,
                         cudaFuncAttributeMaxDynamicSharedMemorySize, SMEM_TOTAL);
    xorconv_mma_kernel<<<dim3(16, 2, BB), 512, SMEM_TOTAL>>>(out);
}

// round 8
// speedup vs baseline: 1.0521x; 1.0521x over previous
#include <cuda_runtime.h>
#include <cuda_fp16.h>
#include <cstdint>
#include <cstddef>

// XOR-conv implicit GEMM, mma.sync fp16 (f32 acc).
// R8: per-wm-group weight pipeline (producer warp + mbarrier full/empty,
// LDG->STS staging). CTA-wide barriers only at the 4 ci-chunk boundaries.
#define BB 32
#define CIN 128
#define HH 64
#define WWD 64
#define COUT 256
#define HOUT 62
#define WOUT 62

__device__ __align__(16) uint16_t g_wbuf[9 * COUT * CIN];            // fp16 (1-2W), [khw][co][ci]
__device__ __align__(16) uint32_t g_xh[(size_t)BB * HH * WWD * 64];  // fp16x2 [b][h][w][ci/2]

__device__ __forceinline__ uint32_t smem_u32(const void* p) {
    uint32_t a;
    asm("{ .reg .u64 t; cvta.to.shared.u64 t, %1; cvt.u32.u64 %0, t; }" : "=r"(a) : "l"(p));
    return a;
}
__device__ __forceinline__ void cpa16(uint32_t dst, const void* src, uint32_t sz) {
    asm volatile("cp.async.cg.shared.global [%0], [%1], 16, %2;"
                 :: "r"(dst), "l"(src), "r"(sz) : "memory");
}
__device__ __forceinline__ void ldsm_x4(uint32_t* r, uint32_t a) {
    asm volatile("ldmatrix.sync.aligned.m8n8.x4.shared.b16 {%0,%1,%2,%3}, [%4];"
                 : "=r"(r[0]), "=r"(r[1]), "=r"(r[2]), "=r"(r[3]) : "r"(a));
}
__device__ __forceinline__ void mbar_init(uint32_t a, uint32_t cnt) {
    asm volatile("mbarrier.init.shared.b64 [%0], %1;" :: "r"(a), "r"(cnt) : "memory");
}
__device__ __forceinline__ void mbar_arrive(uint32_t a) {
    asm volatile("mbarrier.arrive.shared.b64 _, [%0];" :: "r"(a) : "memory");
}
__device__ __forceinline__ void mbar_wait(uint32_t a, uint32_t ph) {
    asm volatile(
        "{\n\t.reg .pred P;\n\t"
        "WL_%=:\n\t"
        "mbarrier.try_wait.parity.shared.b64 P, [%0], %1;\n\t"
        "@P bra WD_%=;\n\t"
        "bra WL_%=;\n\t"
        "WD_%=:\n\t}"
        :: "r"(a), "r"(ph) : "memory");
}
#define MMA16816(c, A, b0, b1)                                                \
    asm volatile("mma.sync.aligned.m16n8k16.row.col.f32.f16.f16.f32 "         \
                 "{%0,%1,%2,%3}, {%4,%5,%6,%7}, {%8,%9}, {%0,%1,%2,%3};"      \
                 : "+f"((c)[0]), "+f"((c)[1]), "+f"((c)[2]), "+f"((c)[3])     \
                 : "r"((A)[0]), "r"((A)[1]), "r"((A)[2]), "r"((A)[3]),        \
                   "r"(b0), "r"(b1))

// ---------------- prep ----------------
__global__ void prep_w_kernel(const float* __restrict__ w) {
    int idx = blockIdx.x * 256 + threadIdx.x;
    if (idx < 9 * COUT * CIN) {
        int khw = idx / (COUT * CIN);
        int rem = idx % (COUT * CIN);
        int co = rem >> 7, ci = rem & 127;
        int kh = khw / 3, kw = khw % 3;
        float v = 1.0f - 2.0f * w[(((size_t)co * CIN + ci) * 3 + kh) * 3 + kw];
        g_wbuf[idx] = __half_as_ushort(__float2half_rn(v));
    }
}

__global__ void prep_x_kernel(const float* __restrict__ x) {
    __shared__ float t[CIN][67];
    const int h = blockIdx.x, b = blockIdx.y, tid = threadIdx.x;
#pragma unroll
    for (int i = 0; i < 32; i++) {
        int idx = tid + i * 256;
        int ci = idx >> 6, w = idx & 63;
        t[ci][w] = x[(((size_t)b * CIN + ci) * HH + h) * WWD + w];
    }
    __syncthreads();
#pragma unroll
    for (int i = 0; i < 16; i++) {
        int idx = tid + i * 256;
        int w = idx >> 6, j = idx & 63;
        uint32_t hw2 = ((uint32_t)__half_as_ushort(__float2half_rn(t[2 * j + 1][w])) << 16) |
                       __half_as_ushort(__float2half_rn(t[2 * j][w]));
        g_xh[(((size_t)b * HH + h) * WWD + w) * 64 + j] = hw2;
    }
}

// ---------------- main ----------------
#define POS_STRIDE 80
#define XBUFSZ (6 * 66 * POS_STRIDE)      // 31680
#define X_TOTAL (2 * XBUFSZ)              // 63360
#define SLABSZ 2560                       // 32 rows x 80 B
#define SLAB_OFF X_TOTAL                  // 8 slabs: [wm][slot]
#define BARB_OFF (X_TOTAL + 8 * SLABSZ)   // 83840: 8 full + 8 empty mbarriers
#define SMEM_TOTAL (BARB_OFF + 128)       // 83968

__global__ __launch_bounds__(512, 1)
void xorconv_mma_kernel(float* __restrict__ out) {
    extern __shared__ char smraw[];
    const uint32_t SX = smem_u32(smraw);
    const uint32_t SLB = SX + SLAB_OFF;
    const uint32_t BARB = SX + BARB_OFF;

    const int tid = threadIdx.x;
    const int wid = tid >> 5, lid = tid & 31;
    const int wm = wid & 3;           // 32-co sub-tile
    const int wn = wid >> 2;          // ho row 0..3
    const bool prod = (wn == 0);      // producer warp of its wm group
    const int ho0 = blockIdx.x * 4;
    const int cob = blockIdx.y;       // 128-co block
    const int b = blockIdx.z;

    // barrier addresses for this wm group
    const uint32_t fullB = BARB + wm * 16;         // +slot*8
    const uint32_t emptyB = BARB + 64 + wm * 16;

    if (tid == 0) {
#pragma unroll
        for (int i = 0; i < 8; i++) {
            mbar_init(BARB + i * 8, 32);        // full: producer lanes
            mbar_init(BARB + 64 + i * 8, 128);  // empty: 4 warps x 32
        }
    }
    __syncthreads();

    const int li = lid & 7, g = lid >> 3;
    // A ldsm offsets within a 32-row slab (per mi half)
    const uint32_t aoff0 = (uint32_t)((g & 1) * 8 + li) * POS_STRIDE + (g >> 1) * 16;
    const uint32_t aoff1 = (uint32_t)(16 + (g & 1) * 8 + li) * POS_STRIDE + (g >> 1) * 16;
    uint32_t qb[4];
#pragma unroll
    for (int j = 0; j < 4; j++)
        qb[j] = (uint32_t)(j * 16 + ((g >> 1) & 1) * 8 + li) * POS_STRIDE + (g & 1) * 16;

    float acc[2][8][4];
#pragma unroll
    for (int mi = 0; mi < 2; mi++)
#pragma unroll
        for (int ni = 0; ni < 8; ni++)
#pragma unroll
            for (int e = 0; e < 4; e++) acc[mi][ni][e] = 0.0f;

    auto stage_x = [&](int q) {
        const uint32_t xb = SX + (uint32_t)(q & 1) * XBUFSZ;
#pragma unroll
        for (int i = 0; i < 4; i++) {
            int idx = tid + i * 512;
            if (idx < 1584) {
                int pos = idx >> 2, c4 = idx & 3;
                int hl = pos / 66, w = pos - hl * 66;
                int h = ho0 + hl;
                uint32_t sz = (h < HH && w < WWD) ? 16u : 0u;
                size_t eo = ((((size_t)b * HH + (h & 63)) * WWD + (w & 63)) * 64) + q * 16 + c4 * 4;
                cpa16(xb + (uint32_t)pos * POS_STRIDE + c4 * 16,
                      (const char*)g_xh + eo * 4, sz);
            }
        }
        asm volatile("cp.async.commit_group;" ::: "memory");
    };

    // producer: LDG one unit's 64B row slice per lane
    uint4 v0, v1, v2, v3;
    auto wldg = [&](int u) {
        int q = u / 9, khw = u % 9;
        const uint4* p = (const uint4*)(g_wbuf +
            ((size_t)(khw * COUT + cob * 128 + wm * 32 + lid) * CIN + q * 32));
        v0 = p[0]; v1 = p[1]; v2 = p[2]; v3 = p[3];
    };
    auto wsts = [&](int u) {
        uint32_t d = SLB + (uint32_t)(wm * 2 + (u & 1)) * SLABSZ + (uint32_t)lid * POS_STRIDE;
        *(uint4*)(smraw + (d - SX)) = v0;
        *(uint4*)(smraw + (d - SX) + 16) = v1;
        *(uint4*)(smraw + (d - SX) + 32) = v2;
        *(uint4*)(smraw + (d - SX) + 48) = v3;
    };

    // prologue: producer stages unit 0
    if (prod) {
        mbar_wait(emptyB + 0, 1);    // fresh barrier, parity 1 -> passes
        wldg(0);
        wsts(0);
        mbar_arrive(fullB + 0);
    }

    stage_x(0);

    for (int q = 0; q < 4; q++) {
        asm volatile("cp.async.wait_group 0;" ::: "memory");
        __syncthreads();
        if (q < 3) stage_x(q + 1);

        const uint32_t xb = SX + (uint32_t)(q & 1) * XBUFSZ;

#pragma unroll
        for (int khw = 0; khw < 9; khw++) {
            const int u = q * 9 + khw;
            const int slot = u & 1;
            const uint32_t slab = SLB + (uint32_t)(wm * 2 + slot) * SLABSZ;

            // wait weights ready, load all A fragments, release the slab
            mbar_wait(fullB + slot * 8, (u >> 1) & 1);
            uint32_t af[16];
            ldsm_x4(af + 0,  slab + aoff0);        // ci16=0, mi=0
            ldsm_x4(af + 4,  slab + aoff1);        // ci16=0, mi=1
            ldsm_x4(af + 8,  slab + 32 + aoff0);   // ci16=1, mi=0
            ldsm_x4(af + 12, slab + 32 + aoff1);   // ci16=1, mi=1
            mbar_arrive(emptyB + slot * 8);

            // producer: start next unit's LDG (latency covered by MMAs below)
            if (prod && u < 35) {
                mbar_wait(emptyB + ((u + 1) & 1) * 8, 1 ^ (((u + 1) >> 1) & 1));
                wldg(u + 1);
            }

            const int kh = khw / 3, kw = khw % 3;
            const uint32_t hwoff = (uint32_t)((wn + kh) * 66 + kw) * POS_STRIDE;

            // ci16 = 0
            {
                const uint32_t xsel = xb + hwoff;
                uint32_t* a0 = af;
                uint32_t* a1 = af + 4;
#pragma unroll
                for (int j = 0; j < 4; j++) {
                    uint32_t bx[4];
                    ldsm_x4(bx, xsel + qb[j]);
                    MMA16816(acc[0][2 * j], a0, bx[0], bx[1]);
                    MMA16816(acc[0][2 * j + 1], a0, bx[2], bx[3]);
                    MMA16816(acc[1][2 * j], a1, bx[0], bx[1]);
                    MMA16816(acc[1][2 * j + 1], a1, bx[2], bx[3]);
                }
            }

            // producer: publish next unit mid-iteration
            if (prod && u < 35) {
                wsts(u + 1);
                mbar_arrive(fullB + ((u + 1) & 1) * 8);
            }

            // ci16 = 1
            {
                const uint32_t xsel = xb + 32 + hwoff;
                uint32_t* a0 = af + 8;
                uint32_t* a1 = af + 12;
#pragma unroll
                for (int j = 0; j < 4; j++) {
                    uint32_t bx[4];
                    ldsm_x4(bx, xsel + qb[j]);
                    MMA16816(acc[0][2 * j], a0, bx[0], bx[1]);
                    MMA16816(acc[0][2 * j + 1], a0, bx[2], bx[3]);
                    MMA16816(acc[1][2 * j], a1, bx[0], bx[1]);
                    MMA16816(acc[1][2 * j + 1], a1, bx[2], bx[3]);
                }
            }
        }
    }

    // ---- epilogue (unchanged) ----
    const int row = lid >> 2, qp = lid & 3;
    const int ho = ho0 + wn;
    if (ho < HOUT) {
#pragma unroll
        for (int mi = 0; mi < 2; mi++) {
            const int cor = cob * 128 + wm * 32 + mi * 16 + row;
            float* b0p = out + (((size_t)b * COUT + cor) * HOUT + ho) * WOUT;
            float* b1p = out + (((size_t)b * COUT + cor + 8) * HOUT + ho) * WOUT;
#pragma unroll
            for (int ni = 0; ni < 8; ni++) {
                const int wo = ni * 8 + qp * 2;
                if (wo < WOUT) {
                    *(float2*)(b0p + wo) = make_float2(acc[mi][ni][0], acc[mi][ni][1]);
                    *(float2*)(b1p + wo) = make_float2(acc[mi][ni][2], acc[mi][ni][3]);
                }
            }
        }
    }
}

// ---------------- launch ----------------
extern "C" void kernel_launch(void* const* d_in, const int* in_sizes, int n_in,
                              void* d_out, int out_size) {
    const float* x = (const float*)d_in[0];
    const float* w = (const float*)d_in[1];
    float* out = (float*)d_out;

    prep_w_kernel<<<(9 * COUT * CIN + 255) / 256, 256>>>(w);
    prep_x_kernel<<<dim3(HH, BB), 256>>>(x);

    cudaFuncSetAttribute(xorconv_mma_kernel,
                         cudaFuncAttributeMaxDynamicSharedMemorySize, SMEM_TOTAL);
    xorconv_mma_kernel<<<dim3(16, 2, BB), 512, SMEM_TOTAL>>>(out);
}

// round 9
// speedup vs baseline: 1.1319x; 1.0759x over previous
#include <cuda_runtime.h>
#include <cuda_fp16.h>
#include <cstdint>
#include <cstddef>

// XOR-conv implicit GEMM, mma.sync fp16 (f32 acc).
// R9: R5 pipeline, CTA halved to 256 threads / 83KB smem -> 2 CTAs per SM.
// Co-resident CTA hides the per-iteration refill/barrier dead time that
// R7/R8 restructurings could not remove.
#define BB 32
#define CIN 128
#define HH 64
#define WWD 64
#define COUT 256
#define HOUT 62
#define WOUT 62
#define NTHR 256

__device__ __align__(16) uint16_t g_wbuf[9 * COUT * CIN];            // fp16 (1-2W), [khw][co][ci]
__device__ __align__(16) uint32_t g_xh[(size_t)BB * HH * WWD * 64];  // fp16x2 [b][h][w][ci/2]

__device__ __forceinline__ uint32_t smem_u32(const void* p) {
    uint32_t a;
    asm("{ .reg .u64 t; cvta.to.shared.u64 t, %1; cvt.u32.u64 %0, t; }" : "=r"(a) : "l"(p));
    return a;
}
__device__ __forceinline__ void cpa16(uint32_t dst, const void* src, uint32_t sz) {
    asm volatile("cp.async.cg.shared.global [%0], [%1], 16, %2;"
                 :: "r"(dst), "l"(src), "r"(sz) : "memory");
}
__device__ __forceinline__ void ldsm_x4(uint32_t* r, uint32_t a) {
    asm volatile("ldmatrix.sync.aligned.m8n8.x4.shared.b16 {%0,%1,%2,%3}, [%4];"
                 : "=r"(r[0]), "=r"(r[1]), "=r"(r[2]), "=r"(r[3]) : "r"(a));
}
#define MMA16816(c, A, b0, b1)                                                \
    asm volatile("mma.sync.aligned.m16n8k16.row.col.f32.f16.f16.f32 "         \
                 "{%0,%1,%2,%3}, {%4,%5,%6,%7}, {%8,%9}, {%0,%1,%2,%3};"      \
                 : "+f"((c)[0]), "+f"((c)[1]), "+f"((c)[2]), "+f"((c)[3])     \
                 : "r"((A)[0]), "r"((A)[1]), "r"((A)[2]), "r"((A)[3]),        \
                   "r"(b0), "r"(b1))

// ---------------- prep ----------------
__global__ void prep_w_kernel(const float* __restrict__ w) {
    int idx = blockIdx.x * 256 + threadIdx.x;
    if (idx < 9 * COUT * CIN) {
        int khw = idx / (COUT * CIN);
        int rem = idx % (COUT * CIN);
        int co = rem >> 7, ci = rem & 127;
        int kh = khw / 3, kw = khw % 3;
        float v = 1.0f - 2.0f * w[(((size_t)co * CIN + ci) * 3 + kh) * 3 + kw];
        g_wbuf[idx] = __half_as_ushort(__float2half_rn(v));
    }
}

__global__ void prep_x_kernel(const float* __restrict__ x) {
    __shared__ float t[CIN][67];
    const int h = blockIdx.x, b = blockIdx.y, tid = threadIdx.x;
#pragma unroll
    for (int i = 0; i < 32; i++) {
        int idx = tid + i * 256;
        int ci = idx >> 6, w = idx & 63;
        t[ci][w] = x[(((size_t)b * CIN + ci) * HH + h) * WWD + w];
    }
    __syncthreads();
#pragma unroll
    for (int i = 0; i < 16; i++) {
        int idx = tid + i * 256;
        int w = idx >> 6, j = idx & 63;
        uint32_t hw2 = ((uint32_t)__half_as_ushort(__float2half_rn(t[2 * j + 1][w])) << 16) |
                       __half_as_ushort(__float2half_rn(t[2 * j][w]));
        g_xh[(((size_t)b * HH + h) * WWD + w) * 64 + j] = hw2;
    }
}

// ---------------- main ----------------
// smem: x: 2 bufs x (4*66*80) = 42240 ; w: 4 bufs x (128*80) = 40960
#define POS_STRIDE 80
#define XBUFSZ (4 * 66 * POS_STRIDE)      // 21120
#define X_TOTAL (2 * XBUFSZ)              // 42240
#define WBUFSZ (128 * POS_STRIDE)         // 10240
#define SW_OFF X_TOTAL
#define SMEM_TOTAL (X_TOTAL + 4 * WBUFSZ) // 83200

__global__ __launch_bounds__(NTHR, 2)
void xorconv_mma_kernel(float* __restrict__ out) {
    extern __shared__ char smraw[];
    const uint32_t SX = smem_u32(smraw);
    const uint32_t SW = SX + SW_OFF;

    const int tid = threadIdx.x;
    const int wid = tid >> 5, lid = tid & 31;
    const int wm = wid & 3;           // 32-co sub-tile
    const int wn = wid >> 2;          // ho row 0..1
    const int ho0 = blockIdx.x * 2;
    const int co0 = blockIdx.y * 128;
    const int b = blockIdx.z;

    const int li = lid & 7, g = lid >> 3;
    // A (weights): [m0-7 k0-7, m8-15 k0-7, m0-7 k8-15, m8-15 k8-15]
    const uint32_t aoff0 = (uint32_t)(wm * 32 + 0 * 16 + (g & 1) * 8 + li) * POS_STRIDE + (g >> 1) * 16;
    const uint32_t aoff1 = (uint32_t)(wm * 32 + 1 * 16 + (g & 1) * 8 + li) * POS_STRIDE + (g >> 1) * 16;
    // B (x): [n0-7 k0-7, n0-7 k8-15, n8-15 k0-7, n8-15 k8-15]
    uint32_t qb[4];
#pragma unroll
    for (int j = 0; j < 4; j++)
        qb[j] = (uint32_t)(j * 16 + ((g >> 1) & 1) * 8 + li) * POS_STRIDE + (g & 1) * 16;

    float acc[2][8][4];
#pragma unroll
    for (int mi = 0; mi < 2; mi++)
#pragma unroll
        for (int ni = 0; ni < 8; ni++)
#pragma unroll
            for (int e = 0; e < 4; e++) acc[mi][ni][e] = 0.0f;

    // ---- staging ----
    auto stage_x = [&](int ci0q) {   // 32 ci (16 words), 4 rows, into xbuf[ci0q&1]
        const uint32_t xb = SX + (uint32_t)(ci0q & 1) * XBUFSZ;
#pragma unroll
        for (int i = 0; i < 5; i++) {
            int idx = tid + i * NTHR;
            if (idx < 1056) {                     // 4*66 pos x 4 c4
                int pos = idx >> 2, c4 = idx & 3;
                int hl = pos / 66, w = pos - hl * 66;
                int h = ho0 + hl;                 // <= 60+3 = 63, always in range
                uint32_t sz = (w < WWD) ? 16u : 0u;
                size_t eo = ((((size_t)b * HH + h) * WWD + (w & 63)) * 64) + ci0q * 16 + c4 * 4;
                cpa16(xb + (uint32_t)pos * POS_STRIDE + c4 * 16,
                      (const char*)g_xh + eo * 4, sz);
            }
        }
    };
    auto stage_w = [&](int ci0q, int khw, int wb) {
        int co = tid >> 1, half = tid & 1;        // 2 x 16B per thread
        const char* src = (const char*)g_wbuf +
            (((size_t)(khw * COUT + co0 + co)) * CIN + ci0q * 32) * 2 + half * 32;
        uint32_t dst = SW + (uint32_t)wb * WBUFSZ + (uint32_t)co * POS_STRIDE + half * 32;
        cpa16(dst, src, 16);
        cpa16(dst + 16, src + 16, 16);
    };
    auto issue_unit = [&](int u) {
        if (u < 36) {
            int ci0q = u / 9, khw = u % 9;
            if (khw == 0) stage_x(ci0q);
            stage_w(ci0q, khw, u & 3);
        }
        asm volatile("cp.async.commit_group;" ::: "memory");  // always: group count aligned
    };

    issue_unit(0);
    issue_unit(1);
    issue_unit(2);

    for (int it = 0; it < 36; it++) {
        asm volatile("cp.async.wait_group 2;" ::: "memory");
        __syncthreads();
        issue_unit(it + 3);

        const int ci0q = it / 9, khw = it % 9;
        const int kh = khw / 3, kw = khw % 3;
        const uint32_t xb = SX + (uint32_t)(ci0q & 1) * XBUFSZ;
        const uint32_t wb = SW + (uint32_t)(it & 3) * WBUFSZ;
        const uint32_t hwoff = (uint32_t)((wn + kh) * 66 + kw) * POS_STRIDE;

#pragma unroll
        for (int ci16 = 0; ci16 < 2; ci16++) {
            const uint32_t xsel = xb + ci16 * 32 + hwoff;
            const uint32_t wsel = wb + ci16 * 32;
            uint32_t a0[4], a1[4];
            ldsm_x4(a0, wsel + aoff0);
            ldsm_x4(a1, wsel + aoff1);
#pragma unroll
            for (int j = 0; j < 4; j++) {
                uint32_t bx[4];
                ldsm_x4(bx, xsel + qb[j]);
                MMA16816(acc[0][2 * j], a0, bx[0], bx[1]);
                MMA16816(acc[0][2 * j + 1], a0, bx[2], bx[3]);
                MMA16816(acc[1][2 * j], a1, bx[0], bx[1]);
                MMA16816(acc[1][2 * j + 1], a1, bx[2], bx[3]);
            }
        }
    }

    // ---- epilogue: direct float2 stores (ho always < 62 here) ----
    const int row = lid >> 2, qp = lid & 3;
    const int ho = ho0 + wn;
#pragma unroll
    for (int mi = 0; mi < 2; mi++) {
        const int cor = co0 + wm * 32 + mi * 16 + row;
        float* b0p = out + (((size_t)b * COUT + cor) * HOUT + ho) * WOUT;
        float* b1p = out + (((size_t)b * COUT + cor + 8) * HOUT + ho) * WOUT;
#pragma unroll
        for (int ni = 0; ni < 8; ni++) {
            const int wo = ni * 8 + qp * 2;
            if (wo < WOUT) {
                *(float2*)(b0p + wo) = make_float2(acc[mi][ni][0], acc[mi][ni][1]);
                *(float2*)(b1p + wo) = make_float2(acc[mi][ni][2], acc[mi][ni][3]);
            }
        }
    }
}

// ---------------- launch ----------------
extern "C" void kernel_launch(void* const* d_in, const int* in_sizes, int n_in,
                              void* d_out, int out_size) {
    const float* x = (const float*)d_in[0];
    const float* w = (const float*)d_in[1];
    float* out = (float*)d_out;

    prep_w_kernel<<<(9 * COUT * CIN + 255) / 256, 256>>>(w);
    prep_x_kernel<<<dim3(HH, BB), 256>>>(x);

    cudaFuncSetAttribute(xorconv_mma_kernel,
                         cudaFuncAttributeMaxDynamicSharedMemorySize, SMEM_TOTAL);
    xorconv_mma_kernel<<<dim3(31, 2, BB), NTHR, SMEM_TOTAL>>>(out);
}